// round 1
// baseline (speedup 1.0000x reference)
#include <cuda_runtime.h>
#include <math.h>

#define NN 50000
#define EE 1600000

// ---------------- scratch (static device globals; no cudaMalloc) ----------------
__device__ int   g_cnt[NN];
__device__ int   g_rowptr[NN + 1];
__device__ int   g_wp[NN];
__device__ int   g_col[EE];
__device__ float g_dinv[NN];
__device__ float g_hb  [(size_t)NN * 64];   // x @ Wb
__device__ float g_xb  [(size_t)NN * 64];   // relu(agg(hb)+bb)
__device__ float g_a2  [(size_t)NN * 64];   // agg(xb)
__device__ float g_xsw1[(size_t)NN * 128];  // [xs1 | xw1]
__device__ float g_a3  [(size_t)NN * 128];  // agg(xsw1)

// ---------------- CSR build ----------------
__global__ void init_cnt_kernel() {
    int i = blockIdx.x * blockDim.x + threadIdx.x;
    if (i < NN) g_cnt[i] = 0;
}

__global__ void count_kernel(const int* __restrict__ edges) {
    int e = blockIdx.x * blockDim.x + threadIdx.x;
    if (e < EE) atomicAdd(&g_cnt[edges[2 * e + 1]], 1);
}

// Single-block exclusive scan over g_cnt -> g_rowptr (+ copy to g_wp), and dinv.
__global__ void scan_kernel() {
    __shared__ int warpsums[32];
    __shared__ int s_carry;
    int tid = threadIdx.x, lane = tid & 31, wid = tid >> 5;
    if (tid == 0) s_carry = 0;
    __syncthreads();
    for (int base = 0; base < NN; base += 1024) {
        int i = base + tid;
        int v = (i < NN) ? g_cnt[i] : 0;
        int x = v;
        #pragma unroll
        for (int off = 1; off < 32; off <<= 1) {
            int y = __shfl_up_sync(0xffffffffu, x, off);
            if (lane >= off) x += y;
        }
        if (lane == 31) warpsums[wid] = x;
        __syncthreads();
        if (wid == 0) {
            int w = warpsums[lane];
            #pragma unroll
            for (int off = 1; off < 32; off <<= 1) {
                int y = __shfl_up_sync(0xffffffffu, w, off);
                if (lane >= off) w += y;
            }
            warpsums[lane] = w;
        }
        __syncthreads();
        int woff = (wid > 0) ? warpsums[wid - 1] : 0;
        int excl = s_carry + woff + x - v;
        if (i < NN) {
            g_rowptr[i] = excl;
            g_wp[i]     = excl;
            g_dinv[i]   = rsqrtf((float)v + 1.0f);
        }
        int total = warpsums[31];
        __syncthreads();
        if (tid == 0) s_carry += total;
        __syncthreads();
    }
    if (threadIdx.x == 0) g_rowptr[NN] = s_carry;
}

__global__ void fill_kernel(const int* __restrict__ edges) {
    int e = blockIdx.x * blockDim.x + threadIdx.x;
    if (e < EE) {
        int s = edges[2 * e];
        int d = edges[2 * e + 1];
        int p = atomicAdd(&g_wp[d], 1);
        g_col[p] = s;
    }
}

// ---------------- aggregation (pull, CSR, one warp per node) ----------------
// out[i] = dinv[i] * ( sum_{e: dst=i} dinv[src]*X[src]  +  dinv[i]*X[i] )  [+bias][relu]
__global__ void agg64_kernel(const float* __restrict__ X, float* __restrict__ out,
                             const float* __restrict__ bias, int relu) {
    int idx  = blockIdx.x * blockDim.x + threadIdx.x;
    int node = idx >> 5;
    if (node >= NN) return;
    int lane = idx & 31;
    float dv = g_dinv[node];
    const float2* Xv = (const float2*)X;
    float2 v = Xv[node * 32 + lane];
    float ax = v.x * dv, ay = v.y * dv;
    int e = g_rowptr[node], end = g_rowptr[node + 1];
    for (; e < end; e++) {
        int s = __ldg(&g_col[e]);
        float ds = g_dinv[s];
        float2 u = Xv[s * 32 + lane];
        ax = fmaf(u.x, ds, ax);
        ay = fmaf(u.y, ds, ay);
    }
    ax *= dv; ay *= dv;
    if (bias) { ax += bias[lane * 2]; ay += bias[lane * 2 + 1]; }
    if (relu) { ax = fmaxf(ax, 0.f); ay = fmaxf(ay, 0.f); }
    ((float2*)out)[node * 32 + lane] = make_float2(ax, ay);
}

__global__ void agg128_kernel(const float* __restrict__ X, float* __restrict__ out) {
    int idx  = blockIdx.x * blockDim.x + threadIdx.x;
    int node = idx >> 5;
    if (node >= NN) return;
    int lane = idx & 31;
    float dv = g_dinv[node];
    const float4* Xv = (const float4*)X;
    float4 v = Xv[node * 32 + lane];
    float a0 = v.x * dv, a1 = v.y * dv, a2 = v.z * dv, a3 = v.w * dv;
    int e = g_rowptr[node], end = g_rowptr[node + 1];
    for (; e < end; e++) {
        int s = __ldg(&g_col[e]);
        float ds = g_dinv[s];
        float4 u = Xv[s * 32 + lane];
        a0 = fmaf(u.x, ds, a0);
        a1 = fmaf(u.y, ds, a1);
        a2 = fmaf(u.z, ds, a2);
        a3 = fmaf(u.w, ds, a3);
    }
    a0 *= dv; a1 *= dv; a2 *= dv; a3 *= dv;
    ((float4*)out)[node * 32 + lane] = make_float4(a0, a1, a2, a3);
}

// ---------------- generic fp32 GEMM: C = [relu](A*B + bias) ----------------
// A: MxK row-major (lda), B: KxN row-major (ldb), C: MxN (ldc). BN=64 per y-block.
// 256 threads, 64x64 tile, 4x4 microtile, BK=16. K % 16 == 0, N-tile fully in range.
__global__ void sgemm_kernel(const float* __restrict__ A, int lda,
                             const float* __restrict__ B, int ldb,
                             const float* __restrict__ bias,
                             float* __restrict__ C, int ldc,
                             int M, int K, int relu) {
    __shared__ float As[16][65];
    __shared__ float Bs[16][68];
    int tid  = threadIdx.x;
    int row0 = blockIdx.x * 64;
    int col0 = blockIdx.y * 64;
    int am = tid >> 2,  ak = (tid & 3)  << 2;   // A tile load: 64 rows x 16 k
    int bk = tid >> 4,  bc = (tid & 15) << 2;   // B tile load: 16 k x 64 cols
    int tr = (tid >> 4) << 2, tc = (tid & 15) << 2;
    float acc[4][4] = {};
    for (int k0 = 0; k0 < K; k0 += 16) {
        float4 av = make_float4(0.f, 0.f, 0.f, 0.f);
        if (row0 + am < M)
            av = *(const float4*)(A + (size_t)(row0 + am) * lda + k0 + ak);
        As[ak + 0][am] = av.x; As[ak + 1][am] = av.y;
        As[ak + 2][am] = av.z; As[ak + 3][am] = av.w;
        float4 bv = *(const float4*)(B + (size_t)(k0 + bk) * ldb + col0 + bc);
        Bs[bk][bc + 0] = bv.x; Bs[bk][bc + 1] = bv.y;
        Bs[bk][bc + 2] = bv.z; Bs[bk][bc + 3] = bv.w;
        __syncthreads();
        #pragma unroll
        for (int k = 0; k < 16; k++) {
            float a0 = As[k][tr + 0], a1 = As[k][tr + 1];
            float a2 = As[k][tr + 2], a3 = As[k][tr + 3];
            float b0 = Bs[k][tc + 0], b1 = Bs[k][tc + 1];
            float b2 = Bs[k][tc + 2], b3 = Bs[k][tc + 3];
            acc[0][0] = fmaf(a0, b0, acc[0][0]); acc[0][1] = fmaf(a0, b1, acc[0][1]);
            acc[0][2] = fmaf(a0, b2, acc[0][2]); acc[0][3] = fmaf(a0, b3, acc[0][3]);
            acc[1][0] = fmaf(a1, b0, acc[1][0]); acc[1][1] = fmaf(a1, b1, acc[1][1]);
            acc[1][2] = fmaf(a1, b2, acc[1][2]); acc[1][3] = fmaf(a1, b3, acc[1][3]);
            acc[2][0] = fmaf(a2, b0, acc[2][0]); acc[2][1] = fmaf(a2, b1, acc[2][1]);
            acc[2][2] = fmaf(a2, b2, acc[2][2]); acc[2][3] = fmaf(a2, b3, acc[2][3]);
            acc[3][0] = fmaf(a3, b0, acc[3][0]); acc[3][1] = fmaf(a3, b1, acc[3][1]);
            acc[3][2] = fmaf(a3, b2, acc[3][2]); acc[3][3] = fmaf(a3, b3, acc[3][3]);
        }
        __syncthreads();
    }
    float bv0 = 0.f, bv1 = 0.f, bv2 = 0.f, bv3 = 0.f;
    if (bias) {
        bv0 = bias[col0 + tc + 0]; bv1 = bias[col0 + tc + 1];
        bv2 = bias[col0 + tc + 2]; bv3 = bias[col0 + tc + 3];
    }
    #pragma unroll
    for (int i = 0; i < 4; i++) {
        int r = row0 + tr + i;
        if (r < M) {
            float4 o;
            o.x = acc[i][0] + bv0; o.y = acc[i][1] + bv1;
            o.z = acc[i][2] + bv2; o.w = acc[i][3] + bv3;
            if (relu) {
                o.x = fmaxf(o.x, 0.f); o.y = fmaxf(o.y, 0.f);
                o.z = fmaxf(o.z, 0.f); o.w = fmaxf(o.w, 0.f);
            }
            *(float4*)(C + (size_t)r * ldc + col0 + tc) = o;
        }
    }
}

// ---------------- launch ----------------
extern "C" void kernel_launch(void* const* d_in, const int* in_sizes, int n_in,
                              void* d_out, int out_size) {
    const float* x    = (const float*)d_in[0];
    const int*   edges = (const int*) d_in[1];
    const float* Wb  = (const float*)d_in[2];
    const float* bb  = (const float*)d_in[3];
    const float* Ws1 = (const float*)d_in[4];
    const float* bs1 = (const float*)d_in[5];
    const float* Ws2 = (const float*)d_in[6];
    const float* bs2 = (const float*)d_in[7];
    const float* Ww1 = (const float*)d_in[8];
    const float* bw1 = (const float*)d_in[9];
    const float* Ww2 = (const float*)d_in[10];
    const float* bw2 = (const float*)d_in[11];
    float* out = (float*)d_out;

    float *hb, *xb, *a2, *xsw1, *a3;
    cudaGetSymbolAddress((void**)&hb,   g_hb);
    cudaGetSymbolAddress((void**)&xb,   g_xb);
    cudaGetSymbolAddress((void**)&a2,   g_a2);
    cudaGetSymbolAddress((void**)&xsw1, g_xsw1);
    cudaGetSymbolAddress((void**)&a3,   g_a3);

    const int EB = (EE + 255) / 256;
    const int AB = (NN * 32 + 255) / 256;
    dim3 g1((NN + 63) / 64, 1);
    dim3 g3((NN + 63) / 64, 10);

    // CSR + degrees
    init_cnt_kernel<<<(NN + 255) / 256, 256>>>();
    count_kernel<<<EB, 256>>>(edges);
    scan_kernel<<<1, 1024>>>();
    fill_kernel<<<EB, 256>>>(edges);

    // Layer b: hb = x @ Wb ; xb = relu(agg(hb) + bb)
    sgemm_kernel<<<g1, 256>>>(x, 640, Wb, 64, nullptr, hb, 64, NN, 640, 0);
    agg64_kernel<<<AB, 256>>>(hb, xb, bb, 1);

    // Shared trunk aggregation: a2 = agg(xb)
    agg64_kernel<<<AB, 256>>>(xb, a2, nullptr, 0);

    // Layers s1/w1: xsw1 = [relu(a2@Ws1+bs1) | relu(a2@Ww1+bw1)]
    sgemm_kernel<<<g1, 256>>>(a2, 64, Ws1, 64, bs1, xsw1,      128, NN, 64, 1);
    sgemm_kernel<<<g1, 256>>>(a2, 64, Ww1, 64, bw1, xsw1 + 64, 128, NN, 64, 1);

    // Fused 128-dim aggregation for both branches: a3 = agg(xsw1)
    agg128_kernel<<<AB, 256>>>(xsw1, a3);

    // Layers s2/w2: outputs (aggregate-then-GEMM, exact same math as reference)
    sgemm_kernel<<<g3, 256>>>(a3,      128, Ws2, 640, bs2, out,                    640, NN, 64, 1);
    sgemm_kernel<<<g3, 256>>>(a3 + 64, 128, Ww2, 640, bw2, out + (size_t)NN * 640, 640, NN, 64, 1);
}

// round 2
// speedup vs baseline: 1.1030x; 1.1030x over previous
#include <cuda_runtime.h>
#include <math.h>

#define NN 50000
#define EE 1600000
#define NBLK 49   // ceil(NN/1024)

typedef unsigned long long u64;

// ---------------- scratch ----------------
__device__ int   g_cnt[NN];
__device__ int   g_rowptr[NN + 1];
__device__ int   g_wp[NN];
__device__ int   g_col[EE];
__device__ float g_dinv[NN];
__device__ int   g_bsum[64];
__device__ int   g_boff[64];
__device__ float g_hb  [(size_t)NN * 64];
__device__ float g_xb  [(size_t)NN * 64];
__device__ float g_a2  [(size_t)NN * 64];
__device__ float g_xsw1[(size_t)NN * 128];
__device__ float g_a3  [(size_t)NN * 128];

// ---------------- f32x2 helpers ----------------
__device__ __forceinline__ u64 fma2(u64 a, u64 b, u64 c) {
    u64 d;
    asm("fma.rn.f32x2 %0, %1, %2, %3;" : "=l"(d) : "l"(a), "l"(b), "l"(c));
    return d;
}
__device__ __forceinline__ u64 pack2(float x) {
    u64 d;
    asm("mov.b64 %0, {%1, %1};" : "=l"(d) : "r"(__float_as_uint(x)));
    return d;
}
__device__ __forceinline__ float2 unpack2(u64 d) {
    float2 f;
    asm("mov.b64 {%0, %1}, %2;" : "=f"(f.x), "=f"(f.y) : "l"(d));
    return f;
}

// ---------------- CSR build ----------------
__global__ void init_cnt_kernel() {
    int i = blockIdx.x * blockDim.x + threadIdx.x;
    if (i < NN) g_cnt[i] = 0;
}

__global__ void count_kernel(const int2* __restrict__ edges) {
    int e = blockIdx.x * blockDim.x + threadIdx.x;
    if (e < EE) atomicAdd(&g_cnt[edges[e].y], 1);
}

// Phase 1: per-block degree sums + dinv
__global__ void degsum_kernel() {
    __shared__ int ws[32];
    int tid = threadIdx.x;
    int i = blockIdx.x * 1024 + tid;
    int v = (i < NN) ? g_cnt[i] : 0;
    if (i < NN) g_dinv[i] = rsqrtf((float)v + 1.0f);
    int x = v;
    #pragma unroll
    for (int off = 16; off; off >>= 1) x += __shfl_down_sync(0xffffffffu, x, off);
    if ((tid & 31) == 0) ws[tid >> 5] = x;
    __syncthreads();
    if (tid < 32) {
        int y = ws[tid];
        #pragma unroll
        for (int off = 16; off; off >>= 1) y += __shfl_down_sync(0xffffffffu, y, off);
        if (tid == 0) g_bsum[blockIdx.x] = y;
    }
}

// Phase 2: scan 49 block sums (1 block, 64 threads)
__global__ void scanb_kernel() {
    __shared__ int s[64];
    int tid = threadIdx.x;
    int v = (tid < NBLK) ? g_bsum[tid] : 0;
    s[tid] = v;
    __syncthreads();
    #pragma unroll
    for (int off = 1; off < 64; off <<= 1) {
        int t = (tid >= off) ? s[tid - off] : 0;
        __syncthreads();
        s[tid] += t;
        __syncthreads();
    }
    g_boff[tid] = s[tid] - v;                  // exclusive
    if (tid == 63) g_rowptr[NN] = s[63];       // total
}

// Phase 3: per-block exclusive scan + global offset -> rowptr, wp
__global__ void scanapply_kernel() {
    __shared__ int warpsums[32];
    int tid = threadIdx.x, lane = tid & 31, wid = tid >> 5;
    int i = blockIdx.x * 1024 + tid;
    int v = (i < NN) ? g_cnt[i] : 0;
    int x = v;
    #pragma unroll
    for (int off = 1; off < 32; off <<= 1) {
        int y = __shfl_up_sync(0xffffffffu, x, off);
        if (lane >= off) x += y;
    }
    if (lane == 31) warpsums[wid] = x;
    __syncthreads();
    if (wid == 0) {
        int w = warpsums[lane];
        #pragma unroll
        for (int off = 1; off < 32; off <<= 1) {
            int y = __shfl_up_sync(0xffffffffu, w, off);
            if (lane >= off) w += y;
        }
        warpsums[lane] = w;
    }
    __syncthreads();
    int excl = g_boff[blockIdx.x] + ((wid > 0) ? warpsums[wid - 1] : 0) + x - v;
    if (i < NN) {
        g_rowptr[i] = excl;
        g_wp[i]     = excl;
    }
}

__global__ void fill_kernel(const int2* __restrict__ edges) {
    int e = blockIdx.x * blockDim.x + threadIdx.x;
    if (e < EE) {
        int2 ed = edges[e];
        int p = atomicAdd(&g_wp[ed.y], 1);
        g_col[p] = ed.x;
    }
}

// ---------------- aggregation (pull, CSR, one warp per node) ----------------
__global__ void agg64_kernel(const float* __restrict__ X, float* __restrict__ out,
                             const float* __restrict__ bias, int relu) {
    int idx  = blockIdx.x * blockDim.x + threadIdx.x;
    int node = idx >> 5;
    if (node >= NN) return;
    int lane = idx & 31;
    float dv = g_dinv[node];
    const float2* Xv = (const float2*)X;
    float2 v = Xv[node * 32 + lane];
    float ax = v.x * dv, ay = v.y * dv;
    int e = g_rowptr[node], end = g_rowptr[node + 1];
    for (; e < end; e++) {
        int s = __ldg(&g_col[e]);
        float ds = g_dinv[s];
        float2 u = Xv[s * 32 + lane];
        ax = fmaf(u.x, ds, ax);
        ay = fmaf(u.y, ds, ay);
    }
    ax *= dv; ay *= dv;
    if (bias) { ax += bias[lane * 2]; ay += bias[lane * 2 + 1]; }
    if (relu) { ax = fmaxf(ax, 0.f); ay = fmaxf(ay, 0.f); }
    ((float2*)out)[node * 32 + lane] = make_float2(ax, ay);
}

__global__ void agg128_kernel(const float* __restrict__ X, float* __restrict__ out) {
    int idx  = blockIdx.x * blockDim.x + threadIdx.x;
    int node = idx >> 5;
    if (node >= NN) return;
    int lane = idx & 31;
    float dv = g_dinv[node];
    const float4* Xv = (const float4*)X;
    float4 v = Xv[node * 32 + lane];
    float a0 = v.x * dv, a1 = v.y * dv, a2 = v.z * dv, a3 = v.w * dv;
    int e = g_rowptr[node], end = g_rowptr[node + 1];
    for (; e < end; e++) {
        int s = __ldg(&g_col[e]);
        float ds = g_dinv[s];
        float4 u = Xv[s * 32 + lane];
        a0 = fmaf(u.x, ds, a0);
        a1 = fmaf(u.y, ds, a1);
        a2 = fmaf(u.z, ds, a2);
        a3 = fmaf(u.w, ds, a3);
    }
    a0 *= dv; a1 *= dv; a2 *= dv; a3 *= dv;
    ((float4*)out)[node * 32 + lane] = make_float4(a0, a1, a2, a3);
}

// ---------------- fp32 GEMM with packed f32x2 FMAs ----------------
// C = [relu](A*B + bias). A: MxK (lda), B: KxN (ldb), C: MxN (ldc).
// 256 threads, 64x64 tile, 4 rows x 4 cols per thread, BK=16.
__global__ void sgemm_kernel(const float* __restrict__ A, int lda,
                             const float* __restrict__ B, int ldb,
                             const float* __restrict__ bias,
                             float* __restrict__ C, int ldc,
                             int M, int K, int relu) {
    __shared__ __align__(16) float As[16][68];
    __shared__ __align__(16) float Bs[16][68];
    int tid  = threadIdx.x;
    int row0 = blockIdx.x * 64;
    int col0 = blockIdx.y * 64;
    int am = tid >> 2,  ak = (tid & 3)  << 2;
    int bk = tid >> 4,  bc = (tid & 15) << 2;
    int tr = (tid >> 4) << 2, tc = (tid & 15) << 2;
    u64 acc[2][4];
    #pragma unroll
    for (int p = 0; p < 2; p++)
        #pragma unroll
        for (int c = 0; c < 4; c++) acc[p][c] = 0ull;

    for (int k0 = 0; k0 < K; k0 += 16) {
        float4 av = make_float4(0.f, 0.f, 0.f, 0.f);
        if (row0 + am < M)
            av = *(const float4*)(A + (size_t)(row0 + am) * lda + k0 + ak);
        As[ak + 0][am] = av.x; As[ak + 1][am] = av.y;
        As[ak + 2][am] = av.z; As[ak + 3][am] = av.w;
        float4 bv = *(const float4*)(B + (size_t)(k0 + bk) * ldb + col0 + bc);
        Bs[bk][bc + 0] = bv.x; Bs[bk][bc + 1] = bv.y;
        Bs[bk][bc + 2] = bv.z; Bs[bk][bc + 3] = bv.w;
        __syncthreads();
        #pragma unroll
        for (int k = 0; k < 16; k++) {
            u64 a01 = *(const u64*)&As[k][tr];        // rows tr, tr+1 packed
            u64 a23 = *(const u64*)&As[k][tr + 2];    // rows tr+2, tr+3 packed
            float2 bA = *(const float2*)&Bs[k][tc];
            float2 bB = *(const float2*)&Bs[k][tc + 2];
            u64 b0 = pack2(bA.x), b1 = pack2(bA.y);
            u64 b2 = pack2(bB.x), b3 = pack2(bB.y);
            acc[0][0] = fma2(a01, b0, acc[0][0]);
            acc[1][0] = fma2(a23, b0, acc[1][0]);
            acc[0][1] = fma2(a01, b1, acc[0][1]);
            acc[1][1] = fma2(a23, b1, acc[1][1]);
            acc[0][2] = fma2(a01, b2, acc[0][2]);
            acc[1][2] = fma2(a23, b2, acc[1][2]);
            acc[0][3] = fma2(a01, b3, acc[0][3]);
            acc[1][3] = fma2(a23, b3, acc[1][3]);
        }
        __syncthreads();
    }

    float bv0 = 0.f, bv1 = 0.f, bv2 = 0.f, bv3 = 0.f;
    if (bias) {
        bv0 = bias[col0 + tc + 0]; bv1 = bias[col0 + tc + 1];
        bv2 = bias[col0 + tc + 2]; bv3 = bias[col0 + tc + 3];
    }
    float2 r0 = unpack2(acc[0][0]), r1 = unpack2(acc[0][1]);
    float2 r2 = unpack2(acc[0][2]), r3 = unpack2(acc[0][3]);
    float2 s0 = unpack2(acc[1][0]), s1 = unpack2(acc[1][1]);
    float2 s2 = unpack2(acc[1][2]), s3 = unpack2(acc[1][3]);
    float rowv[4][4] = {
        { r0.x, r1.x, r2.x, r3.x },
        { r0.y, r1.y, r2.y, r3.y },
        { s0.x, s1.x, s2.x, s3.x },
        { s0.y, s1.y, s2.y, s3.y },
    };
    #pragma unroll
    for (int i = 0; i < 4; i++) {
        int r = row0 + tr + i;
        if (r < M) {
            float4 o;
            o.x = rowv[i][0] + bv0; o.y = rowv[i][1] + bv1;
            o.z = rowv[i][2] + bv2; o.w = rowv[i][3] + bv3;
            if (relu) {
                o.x = fmaxf(o.x, 0.f); o.y = fmaxf(o.y, 0.f);
                o.z = fmaxf(o.z, 0.f); o.w = fmaxf(o.w, 0.f);
            }
            *(float4*)(C + (size_t)r * ldc + col0 + tc) = o;
        }
    }
}

// ---------------- launch ----------------
extern "C" void kernel_launch(void* const* d_in, const int* in_sizes, int n_in,
                              void* d_out, int out_size) {
    const float* x     = (const float*)d_in[0];
    const int2*  edges = (const int2*) d_in[1];
    const float* Wb  = (const float*)d_in[2];
    const float* bb  = (const float*)d_in[3];
    const float* Ws1 = (const float*)d_in[4];
    const float* bs1 = (const float*)d_in[5];
    const float* Ws2 = (const float*)d_in[6];
    const float* bs2 = (const float*)d_in[7];
    const float* Ww1 = (const float*)d_in[8];
    const float* bw1 = (const float*)d_in[9];
    const float* Ww2 = (const float*)d_in[10];
    const float* bw2 = (const float*)d_in[11];
    float* out = (float*)d_out;

    float *hb, *xb, *a2, *xsw1, *a3;
    cudaGetSymbolAddress((void**)&hb,   g_hb);
    cudaGetSymbolAddress((void**)&xb,   g_xb);
    cudaGetSymbolAddress((void**)&a2,   g_a2);
    cudaGetSymbolAddress((void**)&xsw1, g_xsw1);
    cudaGetSymbolAddress((void**)&a3,   g_a3);

    const int EB = (EE + 255) / 256;
    const int AB = (NN * 32 + 255) / 256;
    dim3 g1((NN + 63) / 64, 1);
    dim3 g3((NN + 63) / 64, 10);

    // CSR + degrees
    init_cnt_kernel<<<(NN + 255) / 256, 256>>>();
    count_kernel<<<EB, 256>>>(edges);
    degsum_kernel<<<NBLK, 1024>>>();
    scanb_kernel<<<1, 64>>>();
    scanapply_kernel<<<NBLK, 1024>>>();
    fill_kernel<<<EB, 256>>>(edges);

    // Layer b
    sgemm_kernel<<<g1, 256>>>(x, 640, Wb, 64, nullptr, hb, 64, NN, 640, 0);
    agg64_kernel<<<AB, 256>>>(hb, xb, bb, 1);

    // Shared trunk aggregation
    agg64_kernel<<<AB, 256>>>(xb, a2, nullptr, 0);

    // Layers s1/w1
    sgemm_kernel<<<g1, 256>>>(a2, 64, Ws1, 64, bs1, xsw1,      128, NN, 64, 1);
    sgemm_kernel<<<g1, 256>>>(a2, 64, Ww1, 64, bw1, xsw1 + 64, 128, NN, 64, 1);

    // Fused 128-dim aggregation
    agg128_kernel<<<AB, 256>>>(xsw1, a3);

    // Layers s2/w2
    sgemm_kernel<<<g3, 256>>>(a3,      128, Ws2, 640, bs2, out,                    640, NN, 64, 1);
    sgemm_kernel<<<g3, 256>>>(a3 + 64, 128, Ww2, 640, bw2, out + (size_t)NN * 640, 640, NN, 64, 1);
}

// round 3
// speedup vs baseline: 1.1975x; 1.0857x over previous
#include <cuda_runtime.h>
#include <math.h>

#define NN 50000
#define EE 1600000
#define NBLK 49   // ceil(NN/1024)

typedef unsigned long long u64;

// ---------------- scratch ----------------
__device__ int   g_cnt[NN];
__device__ int   g_rowptr[NN + 1];
__device__ int   g_wp[NN];
__device__ int   g_col[EE];
__device__ float g_dinv[NN];
__device__ int   g_bsum[64];
__device__ int   g_boff[64];
__device__ float g_hb  [(size_t)NN * 64];
__device__ float g_xb  [(size_t)NN * 64];
__device__ float g_a2  [(size_t)NN * 64];
__device__ float g_xsw1[(size_t)NN * 128];
__device__ float g_a3  [(size_t)NN * 128];

// ---------------- f32x2 helpers ----------------
__device__ __forceinline__ u64 fma2(u64 a, u64 b, u64 c) {
    u64 d;
    asm("fma.rn.f32x2 %0, %1, %2, %3;" : "=l"(d) : "l"(a), "l"(b), "l"(c));
    return d;
}
__device__ __forceinline__ u64 pack2(float x) {
    u64 d;
    asm("mov.b64 %0, {%1, %1};" : "=l"(d) : "r"(__float_as_uint(x)));
    return d;
}
__device__ __forceinline__ float2 unpack2(u64 d) {
    float2 f;
    asm("mov.b64 {%0, %1}, %2;" : "=f"(f.x), "=f"(f.y) : "l"(d));
    return f;
}

// ---------------- CSR build ----------------
__global__ void init_cnt_kernel() {
    int i = blockIdx.x * blockDim.x + threadIdx.x;
    if (i < NN) g_cnt[i] = 0;
}

__global__ void count_kernel(const int2* __restrict__ edges) {
    int e = blockIdx.x * blockDim.x + threadIdx.x;
    if (e < EE) atomicAdd(&g_cnt[edges[e].y], 1);
}

__global__ void degsum_kernel() {
    __shared__ int ws[32];
    int tid = threadIdx.x;
    int i = blockIdx.x * 1024 + tid;
    int v = (i < NN) ? g_cnt[i] : 0;
    if (i < NN) g_dinv[i] = rsqrtf((float)v + 1.0f);
    int x = v;
    #pragma unroll
    for (int off = 16; off; off >>= 1) x += __shfl_down_sync(0xffffffffu, x, off);
    if ((tid & 31) == 0) ws[tid >> 5] = x;
    __syncthreads();
    if (tid < 32) {
        int y = ws[tid];
        #pragma unroll
        for (int off = 16; off; off >>= 1) y += __shfl_down_sync(0xffffffffu, y, off);
        if (tid == 0) g_bsum[blockIdx.x] = y;
    }
}

__global__ void scanb_kernel() {
    __shared__ int s[64];
    int tid = threadIdx.x;
    int v = (tid < NBLK) ? g_bsum[tid] : 0;
    s[tid] = v;
    __syncthreads();
    #pragma unroll
    for (int off = 1; off < 64; off <<= 1) {
        int t = (tid >= off) ? s[tid - off] : 0;
        __syncthreads();
        s[tid] += t;
        __syncthreads();
    }
    g_boff[tid] = s[tid] - v;
    if (tid == 63) g_rowptr[NN] = s[63];
}

__global__ void scanapply_kernel() {
    __shared__ int warpsums[32];
    int tid = threadIdx.x, lane = tid & 31, wid = tid >> 5;
    int i = blockIdx.x * 1024 + tid;
    int v = (i < NN) ? g_cnt[i] : 0;
    int x = v;
    #pragma unroll
    for (int off = 1; off < 32; off <<= 1) {
        int y = __shfl_up_sync(0xffffffffu, x, off);
        if (lane >= off) x += y;
    }
    if (lane == 31) warpsums[wid] = x;
    __syncthreads();
    if (wid == 0) {
        int w = warpsums[lane];
        #pragma unroll
        for (int off = 1; off < 32; off <<= 1) {
            int y = __shfl_up_sync(0xffffffffu, w, off);
            if (lane >= off) w += y;
        }
        warpsums[lane] = w;
    }
    __syncthreads();
    int excl = g_boff[blockIdx.x] + ((wid > 0) ? warpsums[wid - 1] : 0) + x - v;
    if (i < NN) {
        g_rowptr[i] = excl;
        g_wp[i]     = excl;
    }
}

__global__ void fill_kernel(const int2* __restrict__ edges) {
    int e = blockIdx.x * blockDim.x + threadIdx.x;
    if (e < EE) {
        int2 ed = edges[e];
        int p = atomicAdd(&g_wp[ed.y], 1);
        g_col[p] = ed.x;
    }
}

// ---------------- aggregation (pull, CSR, one warp per node) ----------------
__global__ void agg64_kernel(const float* __restrict__ X, float* __restrict__ out,
                             const float* __restrict__ bias, int relu) {
    int idx  = blockIdx.x * blockDim.x + threadIdx.x;
    int node = idx >> 5;
    if (node >= NN) return;
    int lane = idx & 31;
    float dv = g_dinv[node];
    const float2* Xv = (const float2*)X;
    float2 v = Xv[node * 32 + lane];
    float ax = v.x * dv, ay = v.y * dv;
    int e = g_rowptr[node], end = g_rowptr[node + 1];
    for (; e < end; e++) {
        int s = __ldg(&g_col[e]);
        float ds = g_dinv[s];
        float2 u = Xv[s * 32 + lane];
        ax = fmaf(u.x, ds, ax);
        ay = fmaf(u.y, ds, ay);
    }
    ax *= dv; ay *= dv;
    if (bias) { ax += bias[lane * 2]; ay += bias[lane * 2 + 1]; }
    if (relu) { ax = fmaxf(ax, 0.f); ay = fmaxf(ay, 0.f); }
    ((float2*)out)[node * 32 + lane] = make_float2(ax, ay);
}

__global__ void agg128_kernel(const float* __restrict__ X, float* __restrict__ out) {
    int idx  = blockIdx.x * blockDim.x + threadIdx.x;
    int node = idx >> 5;
    if (node >= NN) return;
    int lane = idx & 31;
    float dv = g_dinv[node];
    const float4* Xv = (const float4*)X;
    float4 v = Xv[node * 32 + lane];
    float a0 = v.x * dv, a1 = v.y * dv, a2 = v.z * dv, a3 = v.w * dv;
    int e = g_rowptr[node], end = g_rowptr[node + 1];
    for (; e < end; e++) {
        int s = __ldg(&g_col[e]);
        float ds = g_dinv[s];
        float4 u = Xv[s * 32 + lane];
        a0 = fmaf(u.x, ds, a0);
        a1 = fmaf(u.y, ds, a1);
        a2 = fmaf(u.z, ds, a2);
        a3 = fmaf(u.w, ds, a3);
    }
    a0 *= dv; a1 *= dv; a2 *= dv; a3 *= dv;
    ((float4*)out)[node * 32 + lane] = make_float4(a0, a1, a2, a3);
}

// ---------------- fp32 GEMM, f32x2 FMAs, 128xBN tile, 8x8 microtile ----------------
// C = [relu](A*B + bias). A: MxK (lda) row-major. B: KxN row-major.
// Optional fused B: if B1 != nullptr, logical B = [B0 | B1] each 64 wide (ldb=64),
// bias = [bias0 | bias1]. THREADS = 16 * (BN/8).
template<int BN, int THREADS>
__global__ void __launch_bounds__(THREADS)
gemm_tile_kernel(const float* __restrict__ A, int lda,
                 const float* __restrict__ B0, const float* __restrict__ B1, int ldb,
                 const float* __restrict__ bias0, const float* __restrict__ bias1,
                 float* __restrict__ C, int ldc,
                 int M, int K, int relu) {
    constexpr int COLT = BN / 8;               // thread cols
    __shared__ __align__(16) float As[16][132];
    __shared__ __align__(16) float Bs[16][BN + 4];

    int tid  = threadIdx.x;
    int row0 = blockIdx.x * 128;
    int col0 = blockIdx.y * BN;
    int tr = (tid / COLT) * 8;
    int tc = (tid % COLT) * 8;

    u64 acc[4][8];
    #pragma unroll
    for (int p = 0; p < 4; p++)
        #pragma unroll
        for (int c = 0; c < 8; c++) acc[p][c] = 0ull;

    constexpr int AF4 = (128 * 16) / 4;        // 512 float4 per A tile
    constexpr int BF4 = (16 * BN) / 4;

    for (int k0 = 0; k0 < K; k0 += 16) {
        // A tile -> As[k][m] (transposed)
        #pragma unroll
        for (int f = 0; f < AF4 / THREADS; f++) {
            int fi  = tid + f * THREADS;
            int row = fi >> 2, kq = (fi & 3) << 2;
            float4 av = make_float4(0.f, 0.f, 0.f, 0.f);
            if (row0 + row < M)
                av = *(const float4*)(A + (size_t)(row0 + row) * lda + k0 + kq);
            As[kq + 0][row] = av.x; As[kq + 1][row] = av.y;
            As[kq + 2][row] = av.z; As[kq + 3][row] = av.w;
        }
        // B tile -> Bs[k][c]
        #pragma unroll
        for (int f = 0; f < BF4 / THREADS; f++) {
            int fi = tid + f * THREADS;
            int bk = fi / (BN / 4);
            int c  = (fi % (BN / 4)) * 4;
            int gc = col0 + c;
            const float* Bp = B0;
            int cc = gc;
            if (B1 != nullptr && gc >= 64) { Bp = B1; cc = gc - 64; }
            float4 bv = *(const float4*)(Bp + (size_t)(k0 + bk) * ldb + cc);
            Bs[bk][c + 0] = bv.x; Bs[bk][c + 1] = bv.y;
            Bs[bk][c + 2] = bv.z; Bs[bk][c + 3] = bv.w;
        }
        __syncthreads();
        #pragma unroll
        for (int k = 0; k < 16; k++) {
            float4 a0 = *(const float4*)&As[k][tr];
            float4 a1 = *(const float4*)&As[k][tr + 4];
            u64 A0 = ((const u64*)&a0)[0];
            u64 A1 = ((const u64*)&a0)[1];
            u64 A2 = ((const u64*)&a1)[0];
            u64 A3 = ((const u64*)&a1)[1];
            float4 bv0 = *(const float4*)&Bs[k][tc];
            float4 bv1 = *(const float4*)&Bs[k][tc + 4];
            u64 b[8];
            b[0] = pack2(bv0.x); b[1] = pack2(bv0.y);
            b[2] = pack2(bv0.z); b[3] = pack2(bv0.w);
            b[4] = pack2(bv1.x); b[5] = pack2(bv1.y);
            b[6] = pack2(bv1.z); b[7] = pack2(bv1.w);
            #pragma unroll
            for (int c = 0; c < 8; c++) {
                acc[0][c] = fma2(A0, b[c], acc[0][c]);
                acc[1][c] = fma2(A1, b[c], acc[1][c]);
                acc[2][c] = fma2(A2, b[c], acc[2][c]);
                acc[3][c] = fma2(A3, b[c], acc[3][c]);
            }
        }
        __syncthreads();
    }

    // bias for my 8 columns
    float bcol[8];
    #pragma unroll
    for (int c = 0; c < 8; c++) {
        int gc = col0 + tc + c;
        float bvv = 0.f;
        if (bias0) {
            if (bias1 != nullptr && gc >= 64) bvv = bias1[gc - 64];
            else bvv = bias0[gc];
        }
        bcol[c] = bvv;
    }

    #pragma unroll
    for (int i = 0; i < 8; i++) {
        int r = row0 + tr + i;
        if (r < M) {
            float v[8];
            #pragma unroll
            for (int c = 0; c < 8; c++) {
                float2 f = unpack2(acc[i >> 1][c]);
                float x = (i & 1) ? f.y : f.x;
                x += bcol[c];
                if (relu) x = fmaxf(x, 0.f);
                v[c] = x;
            }
            float* Cp = C + (size_t)r * ldc + col0 + tc;
            *(float4*)(Cp)     = make_float4(v[0], v[1], v[2], v[3]);
            *(float4*)(Cp + 4) = make_float4(v[4], v[5], v[6], v[7]);
        }
    }
}

// ---------------- launch ----------------
extern "C" void kernel_launch(void* const* d_in, const int* in_sizes, int n_in,
                              void* d_out, int out_size) {
    const float* x     = (const float*)d_in[0];
    const int2*  edges = (const int2*) d_in[1];
    const float* Wb  = (const float*)d_in[2];
    const float* bb  = (const float*)d_in[3];
    const float* Ws1 = (const float*)d_in[4];
    const float* bs1 = (const float*)d_in[5];
    const float* Ws2 = (const float*)d_in[6];
    const float* bs2 = (const float*)d_in[7];
    const float* Ww1 = (const float*)d_in[8];
    const float* bw1 = (const float*)d_in[9];
    const float* Ww2 = (const float*)d_in[10];
    const float* bw2 = (const float*)d_in[11];
    float* out = (float*)d_out;

    float *hb, *xb, *a2, *xsw1, *a3;
    cudaGetSymbolAddress((void**)&hb,   g_hb);
    cudaGetSymbolAddress((void**)&xb,   g_xb);
    cudaGetSymbolAddress((void**)&a2,   g_a2);
    cudaGetSymbolAddress((void**)&xsw1, g_xsw1);
    cudaGetSymbolAddress((void**)&a3,   g_a3);

    const int EB = (EE + 255) / 256;
    const int AB = (NN * 32 + 255) / 256;
    const int MB = (NN + 127) / 128;   // 391

    // CSR + degrees
    init_cnt_kernel<<<(NN + 255) / 256, 256>>>();
    count_kernel<<<EB, 256>>>(edges);
    degsum_kernel<<<NBLK, 1024>>>();
    scanb_kernel<<<1, 64>>>();
    scanapply_kernel<<<NBLK, 1024>>>();
    fill_kernel<<<EB, 256>>>(edges);

    // Layer b: hb = x @ Wb  (M=50000, K=640, N=64)
    gemm_tile_kernel<64, 128><<<dim3(MB, 1), 128>>>(
        x, 640, Wb, nullptr, 64, nullptr, nullptr, hb, 64, NN, 640, 0);
    agg64_kernel<<<AB, 256>>>(hb, xb, bb, 1);

    // Shared trunk aggregation
    agg64_kernel<<<AB, 256>>>(xb, a2, nullptr, 0);

    // Fused s1/w1: xsw1 = relu(a2 @ [Ws1|Ww1] + [bs1|bw1])  (K=64, N=128)
    gemm_tile_kernel<128, 256><<<dim3(MB, 1), 256>>>(
        a2, 64, Ws1, Ww1, 64, bs1, bw1, xsw1, 128, NN, 64, 1);

    // Fused 128-dim aggregation
    agg128_kernel<<<AB, 256>>>(xsw1, a3);

    // Layers s2/w2: outputs (K=64, N=640)
    gemm_tile_kernel<128, 256><<<dim3(MB, 5), 256>>>(
        a3, 128, Ws2, nullptr, 640, bs2, nullptr, out, 640, NN, 64, 1);
    gemm_tile_kernel<128, 256><<<dim3(MB, 5), 256>>>(
        a3 + 64, 128, Ww2, nullptr, 640, bw2, nullptr, out + (size_t)NN * 640, 640, NN, 64, 1);
}